// round 8
// baseline (speedup 1.0000x reference)
#include <cuda_runtime.h>
#include <cstdint>

typedef unsigned int u32;

#define T_KD   4.0f
#define Bsz    4096
#define Pn     12
#define DIN    640
#define Dm     128
#define NBLK_G 32
#define NTILES 416
#define THREADS 512

// ---- SMEM layout (bytes) ----
// misc floats [0,4096): b1[128], b2[128], rinv[128], parts[4][128]
// stage region [4096, 4096+131072): layer1 = 2 stages x {A_hi,A_lo,B_hi,B_lo}(16KB each)
// reused after layer1:
//   Hf (fp32, 64KB)  @ OFF_STG          (stage-0 area)
//   B2 stages        @ OFF_STG + 65536  (stage-1 area): s*32768 + {hi 16KB, lo 16KB}
#define OFF_STG   4096
#define STG_SZ    65536
#define A_HI      0
#define A_LO      16384
#define B_HI      32768
#define B_LO      49152
#define OFF_HF    (OFF_STG)
#define OFF_B2    (OFF_STG + 65536)
#define SMEM_TOTAL (OFF_STG + 2 * STG_SZ)   // 135168 = 132 KB

// ---- scratch ----
__device__ float g_buf[Bsz * Dm];
__device__ float p_buf[Pn * Bsz * Dm];
__device__ float part_dil[Bsz];
__device__ float part_dcl[Bsz];

__device__ __forceinline__ u32 f2tf(float v) {
    u32 r; asm("cvt.rna.tf32.f32 %0, %1;" : "=r"(r) : "f"(v)); return r;
}
__device__ __forceinline__ void split1(float v, u32& h, u32& l) {
    h = f2tf(v);
    l = f2tf(v - __uint_as_float(h));
}
__device__ __forceinline__ void splitf4(float4 v, float4& h, float4& l) {
    u32 hx, lx, hy, ly, hz, lz, hw, lw;
    split1(v.x, hx, lx); split1(v.y, hy, ly);
    split1(v.z, hz, lz); split1(v.w, hw, lw);
    h = make_float4(__uint_as_float(hx), __uint_as_float(hy),
                    __uint_as_float(hz), __uint_as_float(hw));
    l = make_float4(__uint_as_float(lx), __uint_as_float(ly),
                    __uint_as_float(lz), __uint_as_float(lw));
}

#define MMA(c, a, b) \
    asm volatile("mma.sync.aligned.m16n8k8.row.col.f32.tf32.tf32.f32 " \
        "{%0,%1,%2,%3},{%4,%5,%6,%7},{%8,%9},{%0,%1,%2,%3};" \
        : "+f"((c)[0]), "+f"((c)[1]), "+f"((c)[2]), "+f"((c)[3]) \
        : "r"((a)[0]), "r"((a)[1]), "r"((a)[2]), "r"((a)[3]), \
          "r"((b)[0]), "r"((b)[1]))

// one KC=32 chunk, both operands pre-split: pure LDS -> MMA
__device__ __forceinline__ void gemm_chunk(
    const float* __restrict__ Ah, const float* __restrict__ Al,
    const float* __restrict__ Bh, const float* __restrict__ Bl,
    float acc[2][4][4], int lane, int gm2, int wn4)
{
#pragma unroll
    for (int kk = 0; kk < 4; kk++) {
        u32 ah[2][4], al[2][4];
#pragma unroll
        for (int mt = 0; mt < 2; mt++) {
            const size_t so = (size_t)((kk * 8 + gm2 + mt) * 32 + lane) * 4;
            uint4 a = *(const uint4*)(Ah + so);
            ah[mt][0] = a.x; ah[mt][1] = a.y; ah[mt][2] = a.z; ah[mt][3] = a.w;
            uint4 b = *(const uint4*)(Al + so);
            al[mt][0] = b.x; al[mt][1] = b.y; al[mt][2] = b.z; al[mt][3] = b.w;
        }
        u32 bh[4][2], bl[4][2];
#pragma unroll
        for (int nt = 0; nt < 4; nt++) {
            const size_t so = (size_t)((kk * 16 + wn4 + nt) * 32 + lane) * 2;
            uint2 h = *(const uint2*)(Bh + so);
            bh[nt][0] = h.x; bh[nt][1] = h.y;
            uint2 l = *(const uint2*)(Bl + so);
            bl[nt][0] = l.x; bl[nt][1] = l.y;
        }
#pragma unroll
        for (int mt = 0; mt < 2; mt++)
#pragma unroll
            for (int nt = 0; nt < 4; nt++) MMA(acc[mt][nt], ah[mt], bh[nt]);
#pragma unroll
        for (int mt = 0; mt < 2; mt++)
#pragma unroll
            for (int nt = 0; nt < 4; nt++) MMA(acc[mt][nt], al[mt], bh[nt]);
#pragma unroll
        for (int mt = 0; mt < 2; mt++)
#pragma unroll
            for (int nt = 0; nt < 4; nt++) MMA(acc[mt][nt], ah[mt], bl[nt]);
    }
}

// layer-2 variant: A fp32 in SMEM (split in regs), B pre-split
__device__ __forceinline__ void gemm_chunk_asplit(
    const float* __restrict__ Af,
    const float* __restrict__ Bh, const float* __restrict__ Bl,
    float acc[2][4][4], int lane, int gm2, int wn4)
{
#pragma unroll
    for (int kk = 0; kk < 4; kk++) {
        u32 ah[2][4], al[2][4];
#pragma unroll
        for (int mt = 0; mt < 2; mt++) {
            float4 a = *(const float4*)(Af + (size_t)((kk * 8 + gm2 + mt) * 32 + lane) * 4);
            split1(a.x, ah[mt][0], al[mt][0]);
            split1(a.y, ah[mt][1], al[mt][1]);
            split1(a.z, ah[mt][2], al[mt][2]);
            split1(a.w, ah[mt][3], al[mt][3]);
        }
        u32 bh[4][2], bl[4][2];
#pragma unroll
        for (int nt = 0; nt < 4; nt++) {
            const size_t so = (size_t)((kk * 16 + wn4 + nt) * 32 + lane) * 2;
            uint2 h = *(const uint2*)(Bh + so);
            bh[nt][0] = h.x; bh[nt][1] = h.y;
            uint2 l = *(const uint2*)(Bl + so);
            bl[nt][0] = l.x; bl[nt][1] = l.y;
        }
#pragma unroll
        for (int mt = 0; mt < 2; mt++)
#pragma unroll
            for (int nt = 0; nt < 4; nt++) MMA(acc[mt][nt], ah[mt], bh[nt]);
#pragma unroll
        for (int mt = 0; mt < 2; mt++)
#pragma unroll
            for (int nt = 0; nt < 4; nt++) MMA(acc[mt][nt], al[mt], bh[nt]);
#pragma unroll
        for (int mt = 0; mt < 2; mt++)
#pragma unroll
            for (int nt = 0; nt < 4; nt++) MMA(acc[mt][nt], ah[mt], bl[nt]);
    }
}

// fragment-order STS: A-frag layout [kk][gmt][lane]{e0..e3}
__device__ __forceinline__ void stsA(float* p, int arow, int akq, float4 v) {
    const int kk = akq >> 1;
    const int e  = ((akq & 1) << 1) | ((arow >> 3) & 1);
    const int slot0 = ((kk * 8 + (arow >> 4)) * 32 + ((arow & 7) << 2));
    p[(slot0 + 0) * 4 + e] = v.x;
    p[(slot0 + 1) * 4 + e] = v.y;
    p[(slot0 + 2) * 4 + e] = v.z;
    p[(slot0 + 3) * 4 + e] = v.w;
}
// B-frag layout [kk][gnt][lane]{e0,e1}
__device__ __forceinline__ void stsB(float* p, int brow, int bkq, float4 v) {
    const int kk = bkq >> 1;
    const int e  = bkq & 1;
    const int slot0 = ((kk * 16 + (brow >> 3)) * 32 + ((brow & 7) << 2));
    p[(slot0 + 0) * 2 + e] = v.x;
    p[(slot0 + 1) * 2 + e] = v.y;
    p[(slot0 + 2) * 2 + e] = v.z;
    p[(slot0 + 3) * 2 + e] = v.w;
}
__device__ __forceinline__ void stsA2(float* hi, float* lo, int arow, int akq, float4 v) {
    float4 h, l; splitf4(v, h, l);
    stsA(hi, arow, akq, h);
    stsA(lo, arow, akq, l);
}
__device__ __forceinline__ void stsB2(float* hi, float* lo, int brow, int bkq, float4 v) {
    float4 h, l; splitf4(v, h, l);
    stsB(hi, brow, bkq, h);
    stsB(lo, brow, bkq, l);
}

__global__ void __launch_bounds__(THREADS, 1) embed_kernel(
    const float* __restrict__ ebg, const float* __restrict__ ebp,
    const float* __restrict__ gw1, const float* __restrict__ gb1,
    const float* __restrict__ gw2, const float* __restrict__ gb2,
    const float* __restrict__ pw1, const float* __restrict__ pb1,
    const float* __restrict__ pw2, const float* __restrict__ pb2)
{
    extern __shared__ char sm[];
    float* miscf = (float*)sm;
    float* b1s   = miscf;
    float* b2s   = miscf + 128;
    float* rinvs = miscf + 256;
    float* parts = miscf + 384;                 // [4][128]
    float* Hf    = (float*)(sm + OFF_HF);       // 16384 floats (64KB), A-frag layout

    const int t    = threadIdx.x;
    const int wid  = t >> 5, lane = t & 31;
    const int wm   = wid >> 2, wn = wid & 3;
    const int gm2  = wm * 2,   wn4 = wn * 4;
    const int blk  = blockIdx.x;

    const float *X, *W1, *B1v, *W2, *B2v;
    float* OUT;
    int rowbase;
    if (blk < NBLK_G) {
        X = ebg; W1 = gw1; B1v = gb1; W2 = gw2; B2v = gb2;
        OUT = g_buf; rowbase = blk * 128;
    } else {
        X = ebp; W1 = pw1; B1v = pb1; W2 = pw2; B2v = pb2;
        OUT = p_buf; rowbase = (blk - NBLK_G) * 128;
    }

    if (t < 128)      b1s[t] = B1v[t];
    else if (t < 256) b2s[t - 128] = B2v[t - 128];

    // fill-thread indexing: thread covers rows arow0, arow0+64 at k-quad akq
    const int arow0 = t >> 3;       // 0..63
    const int akq   = t & 7;
    const float* xptr  = X  + (size_t)(rowbase + arow0) * DIN + akq * 4;
    const float* w1ptr = W1 + (size_t)arow0 * DIN + akq * 4;
    const float* w2ptr = W2 + (size_t)arow0 * Dm  + akq * 4;

    float acc[2][4][4];
#pragma unroll
    for (int a = 0; a < 2; a++)
#pragma unroll
        for (int b = 0; b < 4; b++)
#pragma unroll
            for (int c = 0; c < 4; c++) acc[a][b][c] = 0.f;

    // ---------------- Layer 1: K = 640, 20 chunks of 32 ------------------
    float4 pax[2], pbx[2];
#pragma unroll
    for (int i = 0; i < 2; i++) {
        pax[i] = *(const float4*)(xptr  + (size_t)(64 * i) * DIN);
        pbx[i] = *(const float4*)(w1ptr + (size_t)(64 * i) * DIN);
    }
    {
        float* S = (float*)(sm + OFF_STG);
#pragma unroll
        for (int i = 0; i < 2; i++) {
            stsA2(S + A_HI / 4, S + A_LO / 4, arow0 + 64 * i, akq, pax[i]);
            stsB2(S + B_HI / 4, S + B_LO / 4, arow0 + 64 * i, akq, pbx[i]);
        }
    }
    __syncthreads();

#pragma unroll 1
    for (int c = 0; c < 20; c++) {
        if (c < 19) {
#pragma unroll
            for (int i = 0; i < 2; i++) {
                pax[i] = *(const float4*)(xptr  + (size_t)(64 * i) * DIN + (c + 1) * 32);
                pbx[i] = *(const float4*)(w1ptr + (size_t)(64 * i) * DIN + (c + 1) * 32);
            }
        }
        const float* S = (const float*)(sm + OFF_STG + (c & 1) * STG_SZ);
        gemm_chunk(S + A_HI / 4, S + A_LO / 4, S + B_HI / 4, S + B_LO / 4,
                   acc, lane, gm2, wn4);
        if (c < 19) {
            float* N = (float*)(sm + OFF_STG + ((c + 1) & 1) * STG_SZ);
#pragma unroll
            for (int i = 0; i < 2; i++) {
                stsA2(N + A_HI / 4, N + A_LO / 4, arow0 + 64 * i, akq, pax[i]);
                stsB2(N + B_HI / 4, N + B_LO / 4, arow0 + 64 * i, akq, pbx[i]);
            }
        }
        __syncthreads();
    }

    // ------- L1 epilogue: H = relu(acc + b1) -> fp32 A-frag layout --------
#pragma unroll
    for (int mt = 0; mt < 2; mt++)
#pragma unroll
        for (int nt = 0; nt < 4; nt++)
#pragma unroll
            for (int rr = 0; rr < 4; rr++) {
                const int m = wm * 32 + mt * 16 + (lane >> 2) + 8 * (rr >> 1);
                const int n = wn * 32 + nt * 8 + 2 * (lane & 3) + (rr & 1);
                float y = fmaxf(acc[mt][nt][rr] + b1s[n], 0.f);
                const int idx = ((((n >> 3) * 8 + (m >> 4)) * 32
                                  + (((m & 7) << 2) | (n & 3))) << 2)
                                + (((n & 4) >> 1) | ((m >> 3) & 1));
                Hf[idx] = y;
            }

    // stage B2 chunk 0 pre-split (stage-1 area; all stage-1 reads done)
#pragma unroll
    for (int i = 0; i < 2; i++)
        pbx[i] = *(const float4*)(w2ptr + (size_t)(64 * i) * Dm);
    {
        float* S = (float*)(sm + OFF_B2);
#pragma unroll
        for (int i = 0; i < 2; i++)
            stsB2(S, S + 4096, arow0 + 64 * i, akq, pbx[i]);
    }

#pragma unroll
    for (int a = 0; a < 2; a++)
#pragma unroll
        for (int b = 0; b < 4; b++)
#pragma unroll
            for (int c = 0; c < 4; c++) acc[a][b][c] = 0.f;
    __syncthreads();

    // ---------------- Layer 2: K = 128, 4 chunks of 32 --------------------
#pragma unroll 1
    for (int c2 = 0; c2 < 4; c2++) {
        if (c2 < 3) {
#pragma unroll
            for (int i = 0; i < 2; i++)
                pbx[i] = *(const float4*)(w2ptr + (size_t)(64 * i) * Dm + (c2 + 1) * 32);
        }
        const float* S = (const float*)(sm + OFF_B2 + (c2 & 1) * 32768);
        gemm_chunk_asplit(Hf + c2 * 4096, S, S + 4096, acc, lane, gm2, wn4);
        if (c2 < 3) {
            float* N = (float*)(sm + OFF_B2 + ((c2 + 1) & 1) * 32768);
#pragma unroll
            for (int i = 0; i < 2; i++)
                stsB2(N, N + 4096, arow0 + 64 * i, akq, pbx[i]);
        }
        __syncthreads();
    }

    // -------- L2 epilogue: bias, row sum-squares, L2 norm, direct store ----
    float s2[2][2] = {{0.f, 0.f}, {0.f, 0.f}};
#pragma unroll
    for (int mt = 0; mt < 2; mt++)
#pragma unroll
        for (int nt = 0; nt < 4; nt++)
#pragma unroll
            for (int rr = 0; rr < 4; rr++) {
                const int n = wn * 32 + nt * 8 + 2 * (lane & 3) + (rr & 1);
                const float y = acc[mt][nt][rr] + b2s[n];
                acc[mt][nt][rr] = y;
                s2[mt][rr >> 1] += y * y;
            }
#pragma unroll
    for (int mt = 0; mt < 2; mt++)
#pragma unroll
        for (int rH = 0; rH < 2; rH++) {
            float v = s2[mt][rH];
            v += __shfl_xor_sync(0xffffffffu, v, 1);
            v += __shfl_xor_sync(0xffffffffu, v, 2);
            if ((lane & 3) == 0) {
                const int m = wm * 32 + mt * 16 + (lane >> 2) + 8 * rH;
                parts[wn * 128 + m] = v;
            }
        }
    __syncthreads();
    if (t < 128)
        rinvs[t] = rsqrtf(parts[t] + parts[128 + t] + parts[256 + t] + parts[384 + t]);
    __syncthreads();

#pragma unroll
    for (int mt = 0; mt < 2; mt++)
#pragma unroll
        for (int rH = 0; rH < 2; rH++) {
            const int m = wm * 32 + mt * 16 + (lane >> 2) + 8 * rH;
            const float rv = rinvs[m];
            float* orow = OUT + (size_t)(rowbase + m) * Dm;
#pragma unroll
            for (int nt = 0; nt < 4; nt++) {
                const int n = wn * 32 + nt * 8 + 2 * (lane & 3);
                float2 y;
                y.x = acc[mt][nt][rH * 2 + 0] * rv;
                y.y = acc[mt][nt][rH * 2 + 1] * rv;
                *(float2*)(orow + n) = y;
            }
        }
}

// ---------------------------------------------------------------------------
// Loss kernels (unchanged; rel_err was 0.0 with these)
// ---------------------------------------------------------------------------
__device__ __forceinline__ float wredsum(float v) {
#pragma unroll
    for (int o = 16; o; o >>= 1) v += __shfl_xor_sync(0xffffffffu, v, o);
    return v;
}
__device__ __forceinline__ float wredmax(float v) {
#pragma unroll
    for (int o = 16; o; o >>= 1) v = fmaxf(v, __shfl_xor_sync(0xffffffffu, v, o));
    return v;
}
__device__ __forceinline__ float symkl4(const float* u, const float* v) {
    const float iT = 1.0f / T_KD;
    float uu[4], vv[4];
    float mu = -1e30f, mv = -1e30f;
#pragma unroll
    for (int q = 0; q < 4; q++) {
        uu[q] = u[q] * iT; vv[q] = v[q] * iT;
        mu = fmaxf(mu, uu[q]); mv = fmaxf(mv, vv[q]);
    }
    mu = wredmax(mu); mv = wredmax(mv);
    float eu[4], ev[4], su = 0.f, sv = 0.f;
#pragma unroll
    for (int q = 0; q < 4; q++) {
        eu[q] = __expf(uu[q] - mu); su += eu[q];
        ev[q] = __expf(vv[q] - mv); sv += ev[q];
    }
    su = wredsum(su); sv = wredsum(sv);
    const float lsu = __logf(su), lsv = __logf(sv);
    const float isu = 1.f / su,  isv = 1.f / sv;
    float a = 0.f;
#pragma unroll
    for (int q = 0; q < 4; q++) {
        const float la = uu[q] - mu - lsu;
        const float lb = vv[q] - mv - lsv;
        a += (eu[q] * isu - ev[q] * isv) * (la - lb);
    }
    return wredsum(a);
}

__global__ void __launch_bounds__(384) loss_kernel() {
    __shared__ float parr[Pn][Dm];
    __shared__ float gs[Dm], pbs[Dm];
    __shared__ float wsum[Pn + 1];
    const int b = blockIdx.x, t = threadIdx.x;
    const int w = t >> 5, lane = t & 31;
    {
        float4 pv = *(const float4*)(p_buf + ((size_t)w * Bsz + b) * Dm + lane * 4);
        *(float4*)(&parr[w][lane * 4]) = pv;
        if (w == 0) {
            float4 gv = *(const float4*)(g_buf + (size_t)b * Dm + lane * 4);
            *(float4*)(&gs[lane * 4]) = gv;
        }
    }
    __syncthreads();
    if (t < Dm) {
        float s = 0.f;
#pragma unroll
        for (int l = 0; l < Pn; l++) s += parr[l][t];
        pbs[t] = s * (1.0f / Pn);
    }
    __syncthreads();
    float du[4], dv[4];
#pragma unroll
    for (int q = 0; q < 4; q++) {
        const int c = lane * 4 + q;
        const float pv = parr[w][c];
        float a = gs[c]  - pv; du[q] = a * a;
        float d = pbs[c] - pv; dv[q] = d * d;
    }
    const float vdcl = symkl4(du, dv);
    if (lane == 0) wsum[w] = vdcl;
    if (w == 0) {
        float u[4], v[4];
#pragma unroll
        for (int q = 0; q < 4; q++) { u[q] = gs[lane * 4 + q]; v[q] = pbs[lane * 4 + q]; }
        const float vdil = symkl4(u, v);
        if (lane == 0) wsum[Pn] = vdil;
    }
    __syncthreads();
    if (t == 0) {
        float dcl = 0.f;
#pragma unroll
        for (int l = 0; l < Pn; l++) dcl += wsum[l];
        const float sc = (T_KD * T_KD) / (float)Dm;
        part_dcl[b] = dcl * sc;
        part_dil[b] = wsum[Pn] * sc;
    }
}

__global__ void __launch_bounds__(256) final_kernel(float* out, int out_size) {
    __shared__ float s1[256], s2[256];
    const int t = threadIdx.x;
    float a = 0.f, c = 0.f;
    for (int i = t; i < Bsz; i += 256) { a += part_dil[i]; c += part_dcl[i]; }
    s1[t] = a; s2[t] = c;
    __syncthreads();
#pragma unroll
    for (int o = 128; o > 0; o >>= 1) {
        if (t < o) { s1[t] += s1[t + o]; s2[t] += s2[t + o]; }
        __syncthreads();
    }
    if (t == 0) {
        if (out_size > 0) out[0] = s1[0];
        if (out_size > 1) out[1] = s2[0] * (1.0f / Pn);
    }
}

extern "C" void kernel_launch(void* const* d_in, const int* in_sizes, int n_in,
                              void* d_out, int out_size) {
    (void)in_sizes; (void)n_in;
    const float* ebg = (const float*)d_in[0];
    const float* ebp = (const float*)d_in[1];
    const float* gw1 = (const float*)d_in[3];
    const float* gb1 = (const float*)d_in[4];
    const float* gw2 = (const float*)d_in[5];
    const float* gb2 = (const float*)d_in[6];
    const float* pw1 = (const float*)d_in[7];
    const float* pb1 = (const float*)d_in[8];
    const float* pw2 = (const float*)d_in[9];
    const float* pb2 = (const float*)d_in[10];

    cudaFuncSetAttribute(embed_kernel,
                         cudaFuncAttributeMaxDynamicSharedMemorySize, SMEM_TOTAL);

    embed_kernel<<<NTILES, THREADS, SMEM_TOTAL>>>(
        ebg, ebp, gw1, gb1, gw2, gb2, pw1, pb1, pw2, pb2);
    loss_kernel<<<Bsz, 384>>>();
    final_kernel<<<1, 256>>>((float*)d_out, out_size);
}

// round 9
// speedup vs baseline: 1.5551x; 1.5551x over previous
#include <cuda_runtime.h>
#include <cstdint>

typedef unsigned int u32;

#define T_KD   4.0f
#define Bsz    4096
#define Pn     12
#define DIN    640
#define Dm     128
#define TM     64                      // tile rows per CTA
#define NBLK_G (Bsz / TM)              // 64
#define NTILES ((Pn + 1) * Bsz / TM)   // 832
#define THREADS 256

// ---- SMEM layout (bytes) ----
// misc floats [0,4096): b1[128], b2[128], rinv[64], parts[4][64]
// layer1 stages [4096, 4096+49152): 2 x (A-frag 8KB + B-frag 16KB)
// after layer1: Hf (A-frag fp32 for H, 32KB) @ OFF_STG
//               B2 stages @ OFF_STG+32768: 2 x 16KB
#define OFF_STG   4096
#define STG_SZ    24576
#define OFF_HF    OFF_STG
#define OFF_B2    (OFF_STG + 32768)
#define SMEM_TOTAL (OFF_B2 + 32768)    // 69632 bytes

// ---- scratch ----
__device__ float g_buf[Bsz * Dm];
__device__ float p_buf[Pn * Bsz * Dm];
__device__ float part_dil[Bsz];
__device__ float part_dcl[Bsz];

__device__ __forceinline__ u32 f2tf(float v) {
    u32 r; asm("cvt.rna.tf32.f32 %0, %1;" : "=r"(r) : "f"(v)); return r;
}
__device__ __forceinline__ void split1(float v, u32& h, u32& l) {
    h = f2tf(v);
    l = f2tf(v - __uint_as_float(h));
}

#define MMA(c, a, b) \
    asm volatile("mma.sync.aligned.m16n8k8.row.col.f32.tf32.tf32.f32 " \
        "{%0,%1,%2,%3},{%4,%5,%6,%7},{%8,%9},{%0,%1,%2,%3};" \
        : "+f"((c)[0]), "+f"((c)[1]), "+f"((c)[2]), "+f"((c)[3]) \
        : "r"((a)[0]), "r"((a)[1]), "r"((a)[2]), "r"((a)[3]), \
          "r"((b)[0]), "r"((b)[1]))

// one KC=32 chunk: 4 k8 steps, 3-pass tf32 emulation, warp tile 32x32,
// A-frag tile has 4 gmt groups (TM=64). fp32 operands, split in regs (R5-proven).
__device__ __forceinline__ void gemm_chunk(
    const float* __restrict__ Ab, const float* __restrict__ Bb,
    float acc[2][4][4], int lane, int gm2, int wn4)
{
#pragma unroll
    for (int kk = 0; kk < 4; kk++) {
        u32 ah[2][4], al[2][4];
#pragma unroll
        for (int mt = 0; mt < 2; mt++) {
            float4 a = *(const float4*)(Ab + (size_t)((kk * 4 + gm2 + mt) * 32 + lane) * 4);
            split1(a.x, ah[mt][0], al[mt][0]);
            split1(a.y, ah[mt][1], al[mt][1]);
            split1(a.z, ah[mt][2], al[mt][2]);
            split1(a.w, ah[mt][3], al[mt][3]);
        }
        u32 bh[4][2], bl[4][2];
#pragma unroll
        for (int nt = 0; nt < 4; nt++) {
            float2 b = *(const float2*)(Bb + (size_t)((kk * 16 + wn4 + nt) * 32 + lane) * 2);
            split1(b.x, bh[nt][0], bl[nt][0]);
            split1(b.y, bh[nt][1], bl[nt][1]);
        }
        // pass-major order: same-acc reuse distance = 8 MMAs
#pragma unroll
        for (int mt = 0; mt < 2; mt++)
#pragma unroll
            for (int nt = 0; nt < 4; nt++) MMA(acc[mt][nt], ah[mt], bh[nt]);
#pragma unroll
        for (int mt = 0; mt < 2; mt++)
#pragma unroll
            for (int nt = 0; nt < 4; nt++) MMA(acc[mt][nt], al[mt], bh[nt]);
#pragma unroll
        for (int mt = 0; mt < 2; mt++)
#pragma unroll
            for (int nt = 0; nt < 4; nt++) MMA(acc[mt][nt], ah[mt], bl[nt]);
    }
}

// fragment-order STS. A-frag layout [kk][gmt(4)][lane]{e0..e3}  (TM=64 rows)
__device__ __forceinline__ void stsA(float* p, int arow, int akq, float4 v) {
    const int kk = akq >> 1;
    const int e  = ((akq & 1) << 1) | ((arow >> 3) & 1);
    const int slot0 = ((kk * 4 + (arow >> 4)) * 32 + ((arow & 7) << 2));
    p[(slot0 + 0) * 4 + e] = v.x;
    p[(slot0 + 1) * 4 + e] = v.y;
    p[(slot0 + 2) * 4 + e] = v.z;
    p[(slot0 + 3) * 4 + e] = v.w;
}
// B-frag layout [kk][gnt(16)][lane]{e0,e1}  (128 cols)
__device__ __forceinline__ void stsB(float* p, int brow, int bkq, float4 v) {
    const int kk = bkq >> 1;
    const int e  = bkq & 1;
    const int slot0 = ((kk * 16 + (brow >> 3)) * 32 + ((brow & 7) << 2));
    p[(slot0 + 0) * 2 + e] = v.x;
    p[(slot0 + 1) * 2 + e] = v.y;
    p[(slot0 + 2) * 2 + e] = v.z;
    p[(slot0 + 3) * 2 + e] = v.w;
}

__global__ void __launch_bounds__(THREADS, 2) embed_kernel(
    const float* __restrict__ ebg, const float* __restrict__ ebp,
    const float* __restrict__ gw1, const float* __restrict__ gb1,
    const float* __restrict__ gw2, const float* __restrict__ gb2,
    const float* __restrict__ pw1, const float* __restrict__ pb1,
    const float* __restrict__ pw2, const float* __restrict__ pb2)
{
    extern __shared__ char sm[];
    float* miscf = (float*)sm;
    float* b1s   = miscf;                 // [128]
    float* b2s   = miscf + 128;           // [128]
    float* rinvs = miscf + 256;           // [64]
    float* parts = miscf + 320;           // [4][64]
    float* Hf    = (float*)(sm + OFF_HF); // 8192 floats (32KB), A-frag layout

    const int t    = threadIdx.x;
    const int wid  = t >> 5, lane = t & 31;
    const int wm   = wid >> 2, wn = wid & 3;   // wm 0..1, wn 0..3
    const int gm2  = wm * 2,   wn4 = wn * 4;
    const int blk  = blockIdx.x;

    const float *X, *W1, *B1v, *W2, *B2v;
    float* OUT;
    int rowbase;
    if (blk < NBLK_G) {
        X = ebg; W1 = gw1; B1v = gb1; W2 = gw2; B2v = gb2;
        OUT = g_buf; rowbase = blk * TM;
    } else {
        X = ebp; W1 = pw1; B1v = pb1; W2 = pw2; B2v = pb2;
        OUT = p_buf; rowbase = (blk - NBLK_G) * TM;
    }

    if (t < 128) b1s[t] = B1v[t];
    else         b2s[t - 128] = B2v[t - 128];

    // loader indexing: thread covers A rows arow0(+32), B rows arow0+32*i, k-quad akq
    const int arow0 = t >> 3;       // 0..31
    const int akq   = t & 7;
    const float* xptr  = X  + (size_t)(rowbase + arow0) * DIN + akq * 4;
    const float* w1ptr = W1 + (size_t)arow0 * DIN + akq * 4;
    const float* w2ptr = W2 + (size_t)arow0 * Dm  + akq * 4;

    float acc[2][4][4];
#pragma unroll
    for (int a = 0; a < 2; a++)
#pragma unroll
        for (int b = 0; b < 4; b++)
#pragma unroll
            for (int c = 0; c < 4; c++) acc[a][b][c] = 0.f;

    // ---------------- Layer 1: K = 640, 20 chunks of 32 ------------------
    float4 pax[2], pbx[4];
#pragma unroll
    for (int i = 0; i < 2; i++)
        pax[i] = *(const float4*)(xptr + (size_t)(32 * i) * DIN);
#pragma unroll
    for (int i = 0; i < 4; i++)
        pbx[i] = *(const float4*)(w1ptr + (size_t)(32 * i) * DIN);
    {
        float* S = (float*)(sm + OFF_STG);
#pragma unroll
        for (int i = 0; i < 2; i++) stsA(S, arow0 + 32 * i, akq, pax[i]);
#pragma unroll
        for (int i = 0; i < 4; i++) stsB(S + 2048, arow0 + 32 * i, akq, pbx[i]);
    }
    __syncthreads();

#pragma unroll 1
    for (int c = 0; c < 20; c++) {
        if (c < 19) {
#pragma unroll
            for (int i = 0; i < 2; i++)
                pax[i] = *(const float4*)(xptr + (size_t)(32 * i) * DIN + (c + 1) * 32);
#pragma unroll
            for (int i = 0; i < 4; i++)
                pbx[i] = *(const float4*)(w1ptr + (size_t)(32 * i) * DIN + (c + 1) * 32);
        }
        const float* S = (const float*)(sm + OFF_STG + (c & 1) * STG_SZ);
        gemm_chunk(S, S + 2048, acc, lane, gm2, wn4);
        if (c < 19) {
            float* N = (float*)(sm + OFF_STG + ((c + 1) & 1) * STG_SZ);
#pragma unroll
            for (int i = 0; i < 2; i++) stsA(N, arow0 + 32 * i, akq, pax[i]);
#pragma unroll
            for (int i = 0; i < 4; i++) stsB(N + 2048, arow0 + 32 * i, akq, pbx[i]);
        }
        __syncthreads();
    }

    // ------- L1 epilogue: H = relu(acc + b1) -> fp32 A-frag layout --------
    // (Hf overlaps stage region; all stage reads completed at loop's final sync)
#pragma unroll
    for (int mt = 0; mt < 2; mt++)
#pragma unroll
        for (int nt = 0; nt < 4; nt++)
#pragma unroll
            for (int rr = 0; rr < 4; rr++) {
                const int m = wm * 32 + mt * 16 + (lane >> 2) + 8 * (rr >> 1);
                const int n = wn * 32 + nt * 8 + 2 * (lane & 3) + (rr & 1);
                float y = fmaxf(acc[mt][nt][rr] + b1s[n], 0.f);
                const int idx = ((((n >> 3) * 4 + (m >> 4)) * 32
                                  + (((m & 7) << 2) | (n & 3))) << 2)
                                + (((n & 4) >> 1) | ((m >> 3) & 1));
                Hf[idx] = y;
            }

    // stage B2 chunk 0 (fp32)
#pragma unroll
    for (int i = 0; i < 4; i++)
        pbx[i] = *(const float4*)(w2ptr + (size_t)(32 * i) * Dm);
    {
        float* S = (float*)(sm + OFF_B2);
#pragma unroll
        for (int i = 0; i < 4; i++) stsB(S, arow0 + 32 * i, akq, pbx[i]);
    }

#pragma unroll
    for (int a = 0; a < 2; a++)
#pragma unroll
        for (int b = 0; b < 4; b++)
#pragma unroll
            for (int c = 0; c < 4; c++) acc[a][b][c] = 0.f;
    __syncthreads();

    // ---------------- Layer 2: K = 128, 4 chunks of 32 --------------------
#pragma unroll 1
    for (int c2 = 0; c2 < 4; c2++) {
        if (c2 < 3) {
#pragma unroll
            for (int i = 0; i < 4; i++)
                pbx[i] = *(const float4*)(w2ptr + (size_t)(32 * i) * Dm + (c2 + 1) * 32);
        }
        const float* S = (const float*)(sm + OFF_B2 + (c2 & 1) * 16384);
        gemm_chunk(Hf + c2 * 2048, S, acc, lane, gm2, wn4);
        if (c2 < 3) {
            float* N = (float*)(sm + OFF_B2 + ((c2 + 1) & 1) * 16384);
#pragma unroll
            for (int i = 0; i < 4; i++) stsB(N, arow0 + 32 * i, akq, pbx[i]);
        }
        __syncthreads();
    }

    // -------- L2 epilogue: bias, row sum-squares, L2 norm, direct store ----
    float s2[2][2] = {{0.f, 0.f}, {0.f, 0.f}};
#pragma unroll
    for (int mt = 0; mt < 2; mt++)
#pragma unroll
        for (int nt = 0; nt < 4; nt++)
#pragma unroll
            for (int rr = 0; rr < 4; rr++) {
                const int n = wn * 32 + nt * 8 + 2 * (lane & 3) + (rr & 1);
                const float y = acc[mt][nt][rr] + b2s[n];
                acc[mt][nt][rr] = y;
                s2[mt][rr >> 1] += y * y;
            }
#pragma unroll
    for (int mt = 0; mt < 2; mt++)
#pragma unroll
        for (int rH = 0; rH < 2; rH++) {
            float v = s2[mt][rH];
            v += __shfl_xor_sync(0xffffffffu, v, 1);
            v += __shfl_xor_sync(0xffffffffu, v, 2);
            if ((lane & 3) == 0) {
                const int m = wm * 32 + mt * 16 + (lane >> 2) + 8 * rH;
                parts[wn * 64 + m] = v;
            }
        }
    __syncthreads();
    if (t < 64)
        rinvs[t] = rsqrtf(parts[t] + parts[64 + t] + parts[128 + t] + parts[192 + t]);
    __syncthreads();

#pragma unroll
    for (int mt = 0; mt < 2; mt++)
#pragma unroll
        for (int rH = 0; rH < 2; rH++) {
            const int m = wm * 32 + mt * 16 + (lane >> 2) + 8 * rH;
            const float rv = rinvs[m];
            float* orow = OUT + (size_t)(rowbase + m) * Dm;
#pragma unroll
            for (int nt = 0; nt < 4; nt++) {
                const int n = wn * 32 + nt * 8 + 2 * (lane & 3);
                float2 y;
                y.x = acc[mt][nt][rH * 2 + 0] * rv;
                y.y = acc[mt][nt][rH * 2 + 1] * rv;
                *(float2*)(orow + n) = y;
            }
        }
}

// ---------------------------------------------------------------------------
// Loss kernels (unchanged; rel_err was 0.0 with these)
// ---------------------------------------------------------------------------
__device__ __forceinline__ float wredsum(float v) {
#pragma unroll
    for (int o = 16; o; o >>= 1) v += __shfl_xor_sync(0xffffffffu, v, o);
    return v;
}
__device__ __forceinline__ float wredmax(float v) {
#pragma unroll
    for (int o = 16; o; o >>= 1) v = fmaxf(v, __shfl_xor_sync(0xffffffffu, v, o));
    return v;
}
__device__ __forceinline__ float symkl4(const float* u, const float* v) {
    const float iT = 1.0f / T_KD;
    float uu[4], vv[4];
    float mu = -1e30f, mv = -1e30f;
#pragma unroll
    for (int q = 0; q < 4; q++) {
        uu[q] = u[q] * iT; vv[q] = v[q] * iT;
        mu = fmaxf(mu, uu[q]); mv = fmaxf(mv, vv[q]);
    }
    mu = wredmax(mu); mv = wredmax(mv);
    float eu[4], ev[4], su = 0.f, sv = 0.f;
#pragma unroll
    for (int q = 0; q < 4; q++) {
        eu[q] = __expf(uu[q] - mu); su += eu[q];
        ev[q] = __expf(vv[q] - mv); sv += ev[q];
    }
    su = wredsum(su); sv = wredsum(sv);
    const float lsu = __logf(su), lsv = __logf(sv);
    const float isu = 1.f / su,  isv = 1.f / sv;
    float a = 0.f;
#pragma unroll
    for (int q = 0; q < 4; q++) {
        const float la = uu[q] - mu - lsu;
        const float lb = vv[q] - mv - lsv;
        a += (eu[q] * isu - ev[q] * isv) * (la - lb);
    }
    return wredsum(a);
}

__global__ void __launch_bounds__(384) loss_kernel() {
    __shared__ float parr[Pn][Dm];
    __shared__ float gs[Dm], pbs[Dm];
    __shared__ float wsum[Pn + 1];
    const int b = blockIdx.x, t = threadIdx.x;
    const int w = t >> 5, lane = t & 31;
    {
        float4 pv = *(const float4*)(p_buf + ((size_t)w * Bsz + b) * Dm + lane * 4);
        *(float4*)(&parr[w][lane * 4]) = pv;
        if (w == 0) {
            float4 gv = *(const float4*)(g_buf + (size_t)b * Dm + lane * 4);
            *(float4*)(&gs[lane * 4]) = gv;
        }
    }
    __syncthreads();
    if (t < Dm) {
        float s = 0.f;
#pragma unroll
        for (int l = 0; l < Pn; l++) s += parr[l][t];
        pbs[t] = s * (1.0f / Pn);
    }
    __syncthreads();
    float du[4], dv[4];
#pragma unroll
    for (int q = 0; q < 4; q++) {
        const int c = lane * 4 + q;
        const float pv = parr[w][c];
        float a = gs[c]  - pv; du[q] = a * a;
        float d = pbs[c] - pv; dv[q] = d * d;
    }
    const float vdcl = symkl4(du, dv);
    if (lane == 0) wsum[w] = vdcl;
    if (w == 0) {
        float u[4], v[4];
#pragma unroll
        for (int q = 0; q < 4; q++) { u[q] = gs[lane * 4 + q]; v[q] = pbs[lane * 4 + q]; }
        const float vdil = symkl4(u, v);
        if (lane == 0) wsum[Pn] = vdil;
    }
    __syncthreads();
    if (t == 0) {
        float dcl = 0.f;
#pragma unroll
        for (int l = 0; l < Pn; l++) dcl += wsum[l];
        const float sc = (T_KD * T_KD) / (float)Dm;
        part_dcl[b] = dcl * sc;
        part_dil[b] = wsum[Pn] * sc;
    }
}

__global__ void __launch_bounds__(256) final_kernel(float* out, int out_size) {
    __shared__ float s1[256], s2[256];
    const int t = threadIdx.x;
    float a = 0.f, c = 0.f;
    for (int i = t; i < Bsz; i += 256) { a += part_dil[i]; c += part_dcl[i]; }
    s1[t] = a; s2[t] = c;
    __syncthreads();
#pragma unroll
    for (int o = 128; o > 0; o >>= 1) {
        if (t < o) { s1[t] += s1[t + o]; s2[t] += s2[t + o]; }
        __syncthreads();
    }
    if (t == 0) {
        if (out_size > 0) out[0] = s1[0];
        if (out_size > 1) out[1] = s2[0] * (1.0f / Pn);
    }
}

extern "C" void kernel_launch(void* const* d_in, const int* in_sizes, int n_in,
                              void* d_out, int out_size) {
    (void)in_sizes; (void)n_in;
    const float* ebg = (const float*)d_in[0];
    const float* ebp = (const float*)d_in[1];
    const float* gw1 = (const float*)d_in[3];
    const float* gb1 = (const float*)d_in[4];
    const float* gw2 = (const float*)d_in[5];
    const float* gb2 = (const float*)d_in[6];
    const float* pw1 = (const float*)d_in[7];
    const float* pb1 = (const float*)d_in[8];
    const float* pw2 = (const float*)d_in[9];
    const float* pb2 = (const float*)d_in[10];

    cudaFuncSetAttribute(embed_kernel,
                         cudaFuncAttributeMaxDynamicSharedMemorySize, SMEM_TOTAL);

    embed_kernel<<<NTILES, THREADS, SMEM_TOTAL>>>(
        ebg, ebp, gw1, gb1, gw2, gb2, pw1, pb1, pw2, pb2);
    loss_kernel<<<Bsz, 384>>>();
    final_kernel<<<1, 256>>>((float*)d_out, out_size);
}

// round 10
// speedup vs baseline: 1.9082x; 1.2270x over previous
#include <cuda_runtime.h>
#include <cstdint>

typedef unsigned int u32;

#define T_KD   4.0f
#define Bsz    4096
#define Pn     12
#define DIN    640
#define Dm     128
#define TM     64                      // tile rows per CTA
#define NBLK_G (Bsz / TM)              // 64
#define NTILES ((Pn + 1) * Bsz / TM)   // 832
#define THREADS 256

// ---- SMEM layout (bytes) ----
#define OFF_STG   4096
#define STG_SZ    24576
#define OFF_HF    OFF_STG
#define OFF_B2    (OFF_STG + 32768)
#define SMEM_TOTAL (OFF_B2 + 32768)    // 69632 bytes

// ---- scratch ----
__device__ float g_buf[Bsz * Dm];
__device__ float p_buf[Pn * Bsz * Dm];
__device__ float part_dil[Bsz];
__device__ float part_dcl[Bsz];

// Mask-based tf32 split (no cvt): hi = tf32 truncation of v (exact tf32 bit
// layout), lo = v - hi (exact in fp32; consumed as tf32 by HW truncation).
__device__ __forceinline__ void split1(float v, u32& h, u32& l) {
    h = __float_as_uint(v) & 0xFFFFE000u;
    l = __float_as_uint(v - __uint_as_float(h));
}

#define MMA(c, a, b) \
    asm volatile("mma.sync.aligned.m16n8k8.row.col.f32.tf32.tf32.f32 " \
        "{%0,%1,%2,%3},{%4,%5,%6,%7},{%8,%9},{%0,%1,%2,%3};" \
        : "+f"((c)[0]), "+f"((c)[1]), "+f"((c)[2]), "+f"((c)[3]) \
        : "r"((a)[0]), "r"((a)[1]), "r"((a)[2]), "r"((a)[3]), \
          "r"((b)[0]), "r"((b)[1]))

// one KC=32 chunk: 4 k8 steps, 3-pass tf32 emulation, warp tile 32x32,
// A-frag tile has 4 gmt groups (TM=64). fp32 operands, mask-split in regs.
__device__ __forceinline__ void gemm_chunk(
    const float* __restrict__ Ab, const float* __restrict__ Bb,
    float acc[2][4][4], int lane, int gm2, int wn4)
{
#pragma unroll
    for (int kk = 0; kk < 4; kk++) {
        u32 ah[2][4], al[2][4];
#pragma unroll
        for (int mt = 0; mt < 2; mt++) {
            float4 a = *(const float4*)(Ab + (size_t)((kk * 4 + gm2 + mt) * 32 + lane) * 4);
            split1(a.x, ah[mt][0], al[mt][0]);
            split1(a.y, ah[mt][1], al[mt][1]);
            split1(a.z, ah[mt][2], al[mt][2]);
            split1(a.w, ah[mt][3], al[mt][3]);
        }
        u32 bh[4][2], bl[4][2];
#pragma unroll
        for (int nt = 0; nt < 4; nt++) {
            float2 b = *(const float2*)(Bb + (size_t)((kk * 16 + wn4 + nt) * 32 + lane) * 2);
            split1(b.x, bh[nt][0], bl[nt][0]);
            split1(b.y, bh[nt][1], bl[nt][1]);
        }
        // pass-major order: same-acc reuse distance = 8 MMAs
#pragma unroll
        for (int mt = 0; mt < 2; mt++)
#pragma unroll
            for (int nt = 0; nt < 4; nt++) MMA(acc[mt][nt], ah[mt], bh[nt]);
#pragma unroll
        for (int mt = 0; mt < 2; mt++)
#pragma unroll
            for (int nt = 0; nt < 4; nt++) MMA(acc[mt][nt], al[mt], bh[nt]);
#pragma unroll
        for (int mt = 0; mt < 2; mt++)
#pragma unroll
            for (int nt = 0; nt < 4; nt++) MMA(acc[mt][nt], ah[mt], bl[nt]);
    }
}

// fragment-order STS. A-frag layout [kk][gmt(4)][lane]{e0..e3}  (TM=64 rows)
__device__ __forceinline__ void stsA(float* p, int arow, int akq, float4 v) {
    const int kk = akq >> 1;
    const int e  = ((akq & 1) << 1) | ((arow >> 3) & 1);
    const int slot0 = ((kk * 4 + (arow >> 4)) * 32 + ((arow & 7) << 2));
    p[(slot0 + 0) * 4 + e] = v.x;
    p[(slot0 + 1) * 4 + e] = v.y;
    p[(slot0 + 2) * 4 + e] = v.z;
    p[(slot0 + 3) * 4 + e] = v.w;
}
// B-frag layout [kk][gnt(16)][lane]{e0,e1}  (128 cols)
__device__ __forceinline__ void stsB(float* p, int brow, int bkq, float4 v) {
    const int kk = bkq >> 1;
    const int e  = bkq & 1;
    const int slot0 = ((kk * 16 + (brow >> 3)) * 32 + ((brow & 7) << 2));
    p[(slot0 + 0) * 2 + e] = v.x;
    p[(slot0 + 1) * 2 + e] = v.y;
    p[(slot0 + 2) * 2 + e] = v.z;
    p[(slot0 + 3) * 2 + e] = v.w;
}

__global__ void __launch_bounds__(THREADS, 2) embed_kernel(
    const float* __restrict__ ebg, const float* __restrict__ ebp,
    const float* __restrict__ gw1, const float* __restrict__ gb1,
    const float* __restrict__ gw2, const float* __restrict__ gb2,
    const float* __restrict__ pw1, const float* __restrict__ pb1,
    const float* __restrict__ pw2, const float* __restrict__ pb2)
{
    extern __shared__ char sm[];
    float* miscf = (float*)sm;
    float* b1s   = miscf;                 // [128]
    float* b2s   = miscf + 128;           // [128]
    float* rinvs = miscf + 256;           // [64]
    float* parts = miscf + 320;           // [4][64]
    float* Hf    = (float*)(sm + OFF_HF); // 8192 floats (32KB), A-frag layout

    const int t    = threadIdx.x;
    const int wid  = t >> 5, lane = t & 31;
    const int wm   = wid >> 2, wn = wid & 3;   // wm 0..1, wn 0..3
    const int gm2  = wm * 2,   wn4 = wn * 4;
    const int blk  = blockIdx.x;

    const float *X, *W1, *B1v, *W2, *B2v;
    float* OUT;
    int rowbase;
    if (blk < NBLK_G) {
        X = ebg; W1 = gw1; B1v = gb1; W2 = gw2; B2v = gb2;
        OUT = g_buf; rowbase = blk * TM;
    } else {
        X = ebp; W1 = pw1; B1v = pb1; W2 = pw2; B2v = pb2;
        OUT = p_buf; rowbase = (blk - NBLK_G) * TM;
    }

    if (t < 128) b1s[t] = B1v[t];
    else         b2s[t - 128] = B2v[t - 128];

    // loader indexing: thread covers A rows arow0(+32), B rows arow0+32*i, k-quad akq
    const int arow0 = t >> 3;       // 0..31
    const int akq   = t & 7;
    const float* xptr  = X  + (size_t)(rowbase + arow0) * DIN + akq * 4;
    const float* w1ptr = W1 + (size_t)arow0 * DIN + akq * 4;
    const float* w2ptr = W2 + (size_t)arow0 * Dm  + akq * 4;

    float acc[2][4][4];
#pragma unroll
    for (int a = 0; a < 2; a++)
#pragma unroll
        for (int b = 0; b < 4; b++)
#pragma unroll
            for (int c = 0; c < 4; c++) acc[a][b][c] = 0.f;

    // ---------------- Layer 1: K = 640, 20 chunks of 32 ------------------
    float4 pax[2], pbx[4];
#pragma unroll
    for (int i = 0; i < 2; i++)
        pax[i] = *(const float4*)(xptr + (size_t)(32 * i) * DIN);
#pragma unroll
    for (int i = 0; i < 4; i++)
        pbx[i] = *(const float4*)(w1ptr + (size_t)(32 * i) * DIN);
    {
        float* S = (float*)(sm + OFF_STG);
#pragma unroll
        for (int i = 0; i < 2; i++) stsA(S, arow0 + 32 * i, akq, pax[i]);
#pragma unroll
        for (int i = 0; i < 4; i++) stsB(S + 2048, arow0 + 32 * i, akq, pbx[i]);
    }
    __syncthreads();

#pragma unroll 1
    for (int c = 0; c < 20; c++) {
        if (c < 19) {
#pragma unroll
            for (int i = 0; i < 2; i++)
                pax[i] = *(const float4*)(xptr + (size_t)(32 * i) * DIN + (c + 1) * 32);
#pragma unroll
            for (int i = 0; i < 4; i++)
                pbx[i] = *(const float4*)(w1ptr + (size_t)(32 * i) * DIN + (c + 1) * 32);
        }
        const float* S = (const float*)(sm + OFF_STG + (c & 1) * STG_SZ);
        gemm_chunk(S, S + 2048, acc, lane, gm2, wn4);
        if (c < 19) {
            float* N = (float*)(sm + OFF_STG + ((c + 1) & 1) * STG_SZ);
#pragma unroll
            for (int i = 0; i < 2; i++) stsA(N, arow0 + 32 * i, akq, pax[i]);
#pragma unroll
            for (int i = 0; i < 4; i++) stsB(N + 2048, arow0 + 32 * i, akq, pbx[i]);
        }
        __syncthreads();
    }

    // ------- L1 epilogue: H = relu(acc + b1) -> fp32 A-frag layout --------
#pragma unroll
    for (int mt = 0; mt < 2; mt++)
#pragma unroll
        for (int nt = 0; nt < 4; nt++)
#pragma unroll
            for (int rr = 0; rr < 4; rr++) {
                const int m = wm * 32 + mt * 16 + (lane >> 2) + 8 * (rr >> 1);
                const int n = wn * 32 + nt * 8 + 2 * (lane & 3) + (rr & 1);
                float y = fmaxf(acc[mt][nt][rr] + b1s[n], 0.f);
                const int idx = ((((n >> 3) * 4 + (m >> 4)) * 32
                                  + (((m & 7) << 2) | (n & 3))) << 2)
                                + (((n & 4) >> 1) | ((m >> 3) & 1));
                Hf[idx] = y;
            }

    // stage B2 chunk 0 (fp32)
#pragma unroll
    for (int i = 0; i < 4; i++)
        pbx[i] = *(const float4*)(w2ptr + (size_t)(32 * i) * Dm);
    {
        float* S = (float*)(sm + OFF_B2);
#pragma unroll
        for (int i = 0; i < 4; i++) stsB(S, arow0 + 32 * i, akq, pbx[i]);
    }

#pragma unroll
    for (int a = 0; a < 2; a++)
#pragma unroll
        for (int b = 0; b < 4; b++)
#pragma unroll
            for (int c = 0; c < 4; c++) acc[a][b][c] = 0.f;
    __syncthreads();

    // ---------------- Layer 2: K = 128, 4 chunks of 32 --------------------
#pragma unroll 1
    for (int c2 = 0; c2 < 4; c2++) {
        if (c2 < 3) {
#pragma unroll
            for (int i = 0; i < 4; i++)
                pbx[i] = *(const float4*)(w2ptr + (size_t)(32 * i) * Dm + (c2 + 1) * 32);
        }
        const float* S = (const float*)(sm + OFF_B2 + (c2 & 1) * 16384);
        gemm_chunk(Hf + c2 * 2048, S, acc, lane, gm2, wn4);
        if (c2 < 3) {
            float* N = (float*)(sm + OFF_B2 + ((c2 + 1) & 1) * 16384);
#pragma unroll
            for (int i = 0; i < 4; i++) stsB(N, arow0 + 32 * i, akq, pbx[i]);
        }
        __syncthreads();
    }

    // -------- L2 epilogue: bias, row sum-squares, L2 norm, direct store ----
    float s2[2][2] = {{0.f, 0.f}, {0.f, 0.f}};
#pragma unroll
    for (int mt = 0; mt < 2; mt++)
#pragma unroll
        for (int nt = 0; nt < 4; nt++)
#pragma unroll
            for (int rr = 0; rr < 4; rr++) {
                const int n = wn * 32 + nt * 8 + 2 * (lane & 3) + (rr & 1);
                const float y = acc[mt][nt][rr] + b2s[n];
                acc[mt][nt][rr] = y;
                s2[mt][rr >> 1] += y * y;
            }
#pragma unroll
    for (int mt = 0; mt < 2; mt++)
#pragma unroll
        for (int rH = 0; rH < 2; rH++) {
            float v = s2[mt][rH];
            v += __shfl_xor_sync(0xffffffffu, v, 1);
            v += __shfl_xor_sync(0xffffffffu, v, 2);
            if ((lane & 3) == 0) {
                const int m = wm * 32 + mt * 16 + (lane >> 2) + 8 * rH;
                parts[wn * 64 + m] = v;
            }
        }
    __syncthreads();
    if (t < 64)
        rinvs[t] = rsqrtf(parts[t] + parts[64 + t] + parts[128 + t] + parts[192 + t]);
    __syncthreads();

#pragma unroll
    for (int mt = 0; mt < 2; mt++)
#pragma unroll
        for (int rH = 0; rH < 2; rH++) {
            const int m = wm * 32 + mt * 16 + (lane >> 2) + 8 * rH;
            const float rv = rinvs[m];
            float* orow = OUT + (size_t)(rowbase + m) * Dm;
#pragma unroll
            for (int nt = 0; nt < 4; nt++) {
                const int n = wn * 32 + nt * 8 + 2 * (lane & 3);
                float2 y;
                y.x = acc[mt][nt][rH * 2 + 0] * rv;
                y.y = acc[mt][nt][rH * 2 + 1] * rv;
                *(float2*)(orow + n) = y;
            }
        }
}

// ---------------------------------------------------------------------------
// Loss kernels (unchanged)
// ---------------------------------------------------------------------------
__device__ __forceinline__ float wredsum(float v) {
#pragma unroll
    for (int o = 16; o; o >>= 1) v += __shfl_xor_sync(0xffffffffu, v, o);
    return v;
}
__device__ __forceinline__ float wredmax(float v) {
#pragma unroll
    for (int o = 16; o; o >>= 1) v = fmaxf(v, __shfl_xor_sync(0xffffffffu, v, o));
    return v;
}
__device__ __forceinline__ float symkl4(const float* u, const float* v) {
    const float iT = 1.0f / T_KD;
    float uu[4], vv[4];
    float mu = -1e30f, mv = -1e30f;
#pragma unroll
    for (int q = 0; q < 4; q++) {
        uu[q] = u[q] * iT; vv[q] = v[q] * iT;
        mu = fmaxf(mu, uu[q]); mv = fmaxf(mv, vv[q]);
    }
    mu = wredmax(mu); mv = wredmax(mv);
    float eu[4], ev[4], su = 0.f, sv = 0.f;
#pragma unroll
    for (int q = 0; q < 4; q++) {
        eu[q] = __expf(uu[q] - mu); su += eu[q];
        ev[q] = __expf(vv[q] - mv); sv += ev[q];
    }
    su = wredsum(su); sv = wredsum(sv);
    const float lsu = __logf(su), lsv = __logf(sv);
    const float isu = 1.f / su,  isv = 1.f / sv;
    float a = 0.f;
#pragma unroll
    for (int q = 0; q < 4; q++) {
        const float la = uu[q] - mu - lsu;
        const float lb = vv[q] - mv - lsv;
        a += (eu[q] * isu - ev[q] * isv) * (la - lb);
    }
    return wredsum(a);
}

__global__ void __launch_bounds__(384) loss_kernel() {
    __shared__ float parr[Pn][Dm];
    __shared__ float gs[Dm], pbs[Dm];
    __shared__ float wsum[Pn + 1];
    const int b = blockIdx.x, t = threadIdx.x;
    const int w = t >> 5, lane = t & 31;
    {
        float4 pv = *(const float4*)(p_buf + ((size_t)w * Bsz + b) * Dm + lane * 4);
        *(float4*)(&parr[w][lane * 4]) = pv;
        if (w == 0) {
            float4 gv = *(const float4*)(g_buf + (size_t)b * Dm + lane * 4);
            *(float4*)(&gs[lane * 4]) = gv;
        }
    }
    __syncthreads();
    if (t < Dm) {
        float s = 0.f;
#pragma unroll
        for (int l = 0; l < Pn; l++) s += parr[l][t];
        pbs[t] = s * (1.0f / Pn);
    }
    __syncthreads();
    float du[4], dv[4];
#pragma unroll
    for (int q = 0; q < 4; q++) {
        const int c = lane * 4 + q;
        const float pv = parr[w][c];
        float a = gs[c]  - pv; du[q] = a * a;
        float d = pbs[c] - pv; dv[q] = d * d;
    }
    const float vdcl = symkl4(du, dv);
    if (lane == 0) wsum[w] = vdcl;
    if (w == 0) {
        float u[4], v[4];
#pragma unroll
        for (int q = 0; q < 4; q++) { u[q] = gs[lane * 4 + q]; v[q] = pbs[lane * 4 + q]; }
        const float vdil = symkl4(u, v);
        if (lane == 0) wsum[Pn] = vdil;
    }
    __syncthreads();
    if (t == 0) {
        float dcl = 0.f;
#pragma unroll
        for (int l = 0; l < Pn; l++) dcl += wsum[l];
        const float sc = (T_KD * T_KD) / (float)Dm;
        part_dcl[b] = dcl * sc;
        part_dil[b] = wsum[Pn] * sc;
    }
}

__global__ void __launch_bounds__(256) final_kernel(float* out, int out_size) {
    __shared__ float s1[256], s2[256];
    const int t = threadIdx.x;
    float a = 0.f, c = 0.f;
    for (int i = t; i < Bsz; i += 256) { a += part_dil[i]; c += part_dcl[i]; }
    s1[t] = a; s2[t] = c;
    __syncthreads();
#pragma unroll
    for (int o = 128; o > 0; o >>= 1) {
        if (t < o) { s1[t] += s1[t + o]; s2[t] += s2[t + o]; }
        __syncthreads();
    }
    if (t == 0) {
        if (out_size > 0) out[0] = s1[0];
        if (out_size > 1) out[1] = s2[0] * (1.0f / Pn);
    }
}

extern "C" void kernel_launch(void* const* d_in, const int* in_sizes, int n_in,
                              void* d_out, int out_size) {
    (void)in_sizes; (void)n_in;
    const float* ebg = (const float*)d_in[0];
    const float* ebp = (const float*)d_in[1];
    const float* gw1 = (const float*)d_in[3];
    const float* gb1 = (const float*)d_in[4];
    const float* gw2 = (const float*)d_in[5];
    const float* gb2 = (const float*)d_in[6];
    const float* pw1 = (const float*)d_in[7];
    const float* pb1 = (const float*)d_in[8];
    const float* pw2 = (const float*)d_in[9];
    const float* pb2 = (const float*)d_in[10];

    cudaFuncSetAttribute(embed_kernel,
                         cudaFuncAttributeMaxDynamicSharedMemorySize, SMEM_TOTAL);

    embed_kernel<<<NTILES, THREADS, SMEM_TOTAL>>>(
        ebg, ebp, gw1, gb1, gw2, gb2, pw1, pb1, pw2, pb2);
    loss_kernel<<<Bsz, 384>>>();
    final_kernel<<<1, 256>>>((float*)d_out, out_size);
}